// round 3
// baseline (speedup 1.0000x reference)
#include <cuda_runtime.h>
#include <cuda_bf16.h>

// DiscriminativeLoss, single fused persistent kernel.
//   data  : [D=32][N=524288] float32 (dim-major), labels: [N] int32 in [0,16)
//
// Pass 1 (segment sums): per 256-point tile, stage data to smem (8x float4
// batched loads), counting-sort point indices by label (1 shared atomic per
// point), thread (k, dr) walks list k accumulating dims dr, dr+16. Partials
// atomicAdd'ed into g_sums/g_counts.
// Device-wide barrier (grid is exactly co-resident: 592 = 148 SMs x 4 blocks,
// enforced by __launch_bounds__(256,4) and 39.4KB smem/block).
// Pass 2 (var term): same staged-load pattern (empirically ~40% more BW than
// interleaved LDG+compute), one point per thread per tile, hinge from smem.
// Last block computes dist + reg terms, writes out[0], resets all globals
// (graph-replay invariant).

#define DD 32
#define KK 16
#define TILE 256
#define XSTR 259   // stride 259 = 256+3; gcd(3,32)=1 -> bank-conflict-free columns
#define GRID 592   // 148 SMs * 4 blocks, all co-resident

__device__ float g_sums[KK * DD];   // [k][d]
__device__ float g_counts[KK];
__device__ float g_var;
__device__ unsigned int g_bar1;
__device__ unsigned int g_done;

__global__ __launch_bounds__(256, 4)
void k_fused(const float* __restrict__ data, const int* __restrict__ labels,
             int npts, float* __restrict__ out) {
    __shared__ float s_x[DD * XSTR];            // 33.2 KB staging tile
    __shared__ unsigned char s_list[KK][TILE];  // 4 KB
    __shared__ int s_cnt[KK];
    __shared__ float s_c[DD * KK];              // centers, [d][k]
    __shared__ float s_red[8];
    __shared__ float s_reg[KK];
    __shared__ unsigned int s_rank;

    const int t  = threadIdx.x;
    const int k  = t >> 4;    // cluster this thread owns (pass 1)
    const int dr = t & 15;    // dims dr and dr+16 (pass 1)
    const int ntiles = npts / TILE;             // 2048

    // ---------------- Pass 1: segment sums ----------------
    float acc0 = 0.f, acc1 = 0.f;
    int ccnt = 0;

    for (int tile = blockIdx.x; tile < ntiles; tile += GRID) {
        const int n0 = tile * TILE;
        __syncthreads();                        // prev phase-B readers done
        if (t < KK) s_cnt[t] = 0;

        #pragma unroll
        for (int j = 0; j < 8; j++) {
            int idx = t + j * 256;              // 0..2047
            int d  = idx >> 6;                  // 64 float4 per dim row
            int n4 = idx & 63;
            float4 v = *reinterpret_cast<const float4*>(
                data + (size_t)d * npts + n0 + (n4 << 2));
            float* p = s_x + d * XSTR + (n4 << 2);
            p[0] = v.x; p[1] = v.y; p[2] = v.z; p[3] = v.w;
        }
        int lab = labels[n0 + t];
        __syncthreads();                        // s_cnt zeroed, s_x filled
        int pos = atomicAdd(&s_cnt[lab], 1);
        s_list[lab][pos] = (unsigned char)t;
        __syncthreads();                        // lists ready

        const int cnt = s_cnt[k];
        const float* r0 = s_x + dr * XSTR;
        const float* r1 = s_x + (dr + 16) * XSTR;
        const unsigned char* lst = s_list[k];
        for (int i = 0; i < cnt; i++) {
            int idx = lst[i];
            acc0 += r0[idx];
            acc1 += r1[idx];
        }
        if (dr == 0) ccnt += cnt;
    }
    atomicAdd(&g_sums[k * DD + dr], acc0);
    atomicAdd(&g_sums[k * DD + dr + 16], acc1);
    if (dr == 0) atomicAdd(&g_counts[k], (float)ccnt);

    // ---------------- Device-wide barrier ----------------
    __syncthreads();
    if (t == 0) {
        __threadfence();
        atomicAdd(&g_bar1, 1u);
        while (atomicAdd(&g_bar1, 0u) < GRID) __nanosleep(64);
        __threadfence();
    }
    __syncthreads();

    // Centers into smem, [d][k] layout (label-distinct banks)
    #pragma unroll
    for (int j = t; j < DD * KK; j += 256) {
        int d = j >> 4, kk = j & 15;
        s_c[j] = g_sums[kk * DD + d] / g_counts[kk];
    }
    __syncthreads();

    // ---------------- Pass 2: var term (staged loads) ----------------
    float vsum = 0.f;
    for (int tile = blockIdx.x; tile < ntiles; tile += GRID) {
        const int n0 = tile * TILE;
        __syncthreads();                        // prev tile's compute done
        #pragma unroll
        for (int j = 0; j < 8; j++) {
            int idx = t + j * 256;
            int d  = idx >> 6;
            int n4 = idx & 63;
            float4 v = *reinterpret_cast<const float4*>(
                data + (size_t)d * npts + n0 + (n4 << 2));
            float* p = s_x + d * XSTR + (n4 << 2);
            p[0] = v.x; p[1] = v.y; p[2] = v.z; p[3] = v.w;
        }
        int lab = labels[n0 + t];
        __syncthreads();                        // s_x filled

        // point t: s_x column bank = (3d + t) % 32 -> lane-distinct; s_c
        // bank = (16d + lab) % 32 -> label-distinct. Conflict-free.
        float a0 = 0.f, a1 = 0.f;
        #pragma unroll
        for (int d = 0; d < DD; d += 2) {
            float d0 = s_c[d * KK + lab] - s_x[d * XSTR + t];
            a0 = fmaf(d0, d0, a0);
            float d1 = s_c[(d + 1) * KK + lab] - s_x[(d + 1) * XSTR + t];
            a1 = fmaf(d1, d1, a1);
        }
        float h = fmaxf(sqrtf(a0 + a1) - 0.5f, 0.f);
        vsum = fmaf(h, h, vsum);
    }

    #pragma unroll
    for (int off = 16; off > 0; off >>= 1)
        vsum += __shfl_down_sync(0xffffffffu, vsum, off);
    if ((t & 31) == 0) s_red[t >> 5] = vsum;
    __syncthreads();
    if (t == 0) {
        float tot = 0.f;
        #pragma unroll
        for (int w = 0; w < 8; w++) tot += s_red[w];
        atomicAdd(&g_var, tot);
        __threadfence();
        s_rank = atomicAdd(&g_done, 1u);
    }
    __syncthreads();

    // ---------------- Epilogue: last block ----------------
    if (s_rank == GRID - 1) {
        __threadfence();
        __syncthreads();                 // make s_red reusable
        if (t < KK) {
            float s = 0.f;
            #pragma unroll
            for (int d = 0; d < DD; d++) { float c = s_c[d * KK + t]; s += c * c; }
            s_reg[t] = sqrtf(s);
        }
        const int i = t >> 4, j = t & 15;
        float dsum = 0.f;
        if (i != j) {
            float sq = 0.f;
            #pragma unroll
            for (int d = 0; d < DD; d++) {
                float df = s_c[d * KK + i] - s_c[d * KK + j];
                sq += df * df;
            }
            float h = fmaxf(3.0f - sqrtf(sq), 0.f);   // 2*DELTA_DIST
            dsum = h * h;
        }
        #pragma unroll
        for (int off = 16; off > 0; off >>= 1)
            dsum += __shfl_down_sync(0xffffffffu, dsum, off);
        if ((t & 31) == 0) s_red[t >> 5] = dsum;
        __syncthreads();
        if (t == 0) {
            float dtot = 0.f;
            #pragma unroll
            for (int w = 0; w < 8; w++) dtot += s_red[w];
            float reg = 0.f;
            #pragma unroll
            for (int kk = 0; kk < KK; kk++) reg += s_reg[kk];
            out[0] = g_var * (1.0f / KK)
                   + dtot * (1.0f / (KK * (KK - 1)))
                   + 0.001f * reg * (1.0f / KK);
            g_var = 0.f;
            g_done = 0u;
            g_bar1 = 0u;
        }
        // re-zero segment accumulators for the next graph replay
        for (int jz = t; jz < KK * DD; jz += 256) g_sums[jz] = 0.f;
        if (t < KK) g_counts[t] = 0.f;
    }
}

extern "C" void kernel_launch(void* const* d_in, const int* in_sizes, int n_in,
                              void* d_out, int out_size) {
    const float* data   = (const float*)d_in[0];
    const int*   labels = (const int*)d_in[1];
    const int    npts   = in_sizes[1];          // 512*1024
    float* out = (float*)d_out;

    k_fused<<<GRID, 256>>>(data, labels, npts, out);
}

// round 4
// speedup vs baseline: 1.1881x; 1.1881x over previous
#include <cuda_runtime.h>
#include <cuda_bf16.h>

// DiscriminativeLoss, two kernels.
//   data  : [D=32][N=524288] float32 (dim-major), labels: [N] int32 in [0,16)
//
// K1 (k_sums): per 256-point tile, stage to smem, counting-sort indices by
// label (1 shared atomic per point), thread (k, dr) walks list k for dims
// dr, dr+16. Demonstrated ~4.7 TB/s.
// K2 (k_var): 4 points per thread; 4 chunks of 8 dims, each chunk loads
// 8 independent float4 LDGs into a register array BEFORE any consumption
// (forces front-batched SASS -> 4KB in flight per warp; R2's version had
// ~1 outstanding load/warp and capped at 3.3 TB/s). Centers from smem
// [d][k] layout (bank-conflict-free). Last block adds dist+reg terms,
// writes out[0], resets globals (graph-replay invariant).

#define DD 32
#define KK 16
#define TILE 256
#define XSTR 259   // odd stride -> phase-B rows spread across banks

__device__ float g_sums[KK * DD];   // [k][d]
__device__ float g_counts[KK];
__device__ float g_var;
__device__ unsigned int g_done;

__global__ __launch_bounds__(256)
void k_sums(const float* __restrict__ data, const int* __restrict__ labels, int npts) {
    __shared__ float s_x[DD * XSTR];            // ~33.2 KB
    __shared__ unsigned char s_list[KK][TILE];  // 4 KB
    __shared__ int s_cnt[KK];

    const int t  = threadIdx.x;
    const int k  = t >> 4;    // cluster this thread owns
    const int dr = t & 15;    // dims dr and dr+16

    float acc0 = 0.f, acc1 = 0.f;
    int ccnt = 0;

    const int ntiles = npts / TILE;             // 2048
    for (int tile = blockIdx.x; tile < ntiles; tile += gridDim.x) {
        const int n0 = tile * TILE;
        __syncthreads();                        // prev phase-B readers done
        if (t < KK) s_cnt[t] = 0;

        #pragma unroll
        for (int j = 0; j < 8; j++) {
            int idx = t + j * 256;              // 0..2047
            int d  = idx >> 6;                  // 64 float4 per dim row
            int n4 = idx & 63;
            float4 v = *reinterpret_cast<const float4*>(
                data + (size_t)d * npts + n0 + (n4 << 2));
            float* p = s_x + d * XSTR + (n4 << 2);
            p[0] = v.x; p[1] = v.y; p[2] = v.z; p[3] = v.w;
        }
        int lab = labels[n0 + t];
        __syncthreads();                        // s_cnt zeroed, s_x filled
        int pos = atomicAdd(&s_cnt[lab], 1);
        s_list[lab][pos] = (unsigned char)t;
        __syncthreads();                        // lists ready

        const int cnt = s_cnt[k];
        const float* r0 = s_x + dr * XSTR;
        const float* r1 = s_x + (dr + 16) * XSTR;
        const unsigned char* lst = s_list[k];
        for (int i = 0; i < cnt; i++) {
            int idx = lst[i];
            acc0 += r0[idx];
            acc1 += r1[idx];
        }
        if (dr == 0) ccnt += cnt;
    }
    atomicAdd(&g_sums[k * DD + dr], acc0);
    atomicAdd(&g_sums[k * DD + dr + 16], acc1);
    if (dr == 0) atomicAdd(&g_counts[k], (float)ccnt);
}

__global__ __launch_bounds__(256, 4)
void k_var(const float* __restrict__ data, const int* __restrict__ labels,
           int npts, float* __restrict__ out) {
    __shared__ float s_c[DD * KK];   // [d][k]: 16-entry rows, conflict-free
    __shared__ float s_red[8];
    __shared__ float s_reg[KK];
    __shared__ unsigned int s_rank;
    const int t = threadIdx.x;

    // Every block derives centers (512 divides, trivial)
    #pragma unroll
    for (int j = t; j < DD * KK; j += 256) {
        int d = j >> 4, kk = j & 15;
        s_c[j] = g_sums[kk * DD + d] / g_counts[kk];
    }
    __syncthreads();

    // One quad of points per thread; grid sized so coverage is exact.
    const int n = (blockIdx.x * 256 + t) * 4;
    const int4 lab = *reinterpret_cast<const int4*>(labels + n);
    float a0 = 0.f, a1 = 0.f, a2 = 0.f, a3 = 0.f;

    #pragma unroll
    for (int c = 0; c < 4; c++) {
        // Loads-only loop: 8 independent LDG.128s issued before any use
        float4 v[8];
        #pragma unroll
        for (int j = 0; j < 8; j++)
            v[j] = *reinterpret_cast<const float4*>(
                data + (size_t)(c * 8 + j) * npts + n);
        // Consume from registers + smem center lookups
        #pragma unroll
        for (int j = 0; j < 8; j++) {
            const float* cr = s_c + (c * 8 + j) * KK;
            float d0 = cr[lab.x] - v[j].x; a0 = fmaf(d0, d0, a0);
            float d1 = cr[lab.y] - v[j].y; a1 = fmaf(d1, d1, a1);
            float d2 = cr[lab.z] - v[j].z; a2 = fmaf(d2, d2, a2);
            float d3 = cr[lab.w] - v[j].w; a3 = fmaf(d3, d3, a3);
        }
    }
    float h0 = fmaxf(sqrtf(a0) - 0.5f, 0.f);
    float h1 = fmaxf(sqrtf(a1) - 0.5f, 0.f);
    float h2 = fmaxf(sqrtf(a2) - 0.5f, 0.f);
    float h3 = fmaxf(sqrtf(a3) - 0.5f, 0.f);
    float vsum = h0 * h0 + h1 * h1 + h2 * h2 + h3 * h3;

    #pragma unroll
    for (int off = 16; off > 0; off >>= 1)
        vsum += __shfl_down_sync(0xffffffffu, vsum, off);
    if ((t & 31) == 0) s_red[t >> 5] = vsum;
    __syncthreads();
    if (t == 0) {
        float tot = 0.f;
        #pragma unroll
        for (int w = 0; w < 8; w++) tot += s_red[w];
        atomicAdd(&g_var, tot);
        __threadfence();
        s_rank = atomicAdd(&g_done, 1u);
    }
    __syncthreads();

    // Last block to finish: dist + reg terms, final write, re-zero for replay
    if (s_rank == gridDim.x - 1) {
        __threadfence();
        __syncthreads();                 // make s_red reusable
        if (t < KK) {
            float s = 0.f;
            #pragma unroll
            for (int d = 0; d < DD; d++) { float c = s_c[d * KK + t]; s += c * c; }
            s_reg[t] = sqrtf(s);
        }
        const int i = t >> 4, j = t & 15;
        float dsum = 0.f;
        if (i != j) {
            float sq = 0.f;
            #pragma unroll
            for (int d = 0; d < DD; d++) {
                float df = s_c[d * KK + i] - s_c[d * KK + j];
                sq += df * df;
            }
            float h = fmaxf(3.0f - sqrtf(sq), 0.f);   // 2*DELTA_DIST
            dsum = h * h;
        }
        #pragma unroll
        for (int off = 16; off > 0; off >>= 1)
            dsum += __shfl_down_sync(0xffffffffu, dsum, off);
        if ((t & 31) == 0) s_red[t >> 5] = dsum;
        __syncthreads();
        if (t == 0) {
            float dtot = 0.f;
            #pragma unroll
            for (int w = 0; w < 8; w++) dtot += s_red[w];
            float reg = 0.f;
            #pragma unroll
            for (int kk = 0; kk < KK; kk++) reg += s_reg[kk];
            out[0] = g_var * (1.0f / KK)
                   + dtot * (1.0f / (KK * (KK - 1)))
                   + 0.001f * reg * (1.0f / KK);
            g_var = 0.f;
            g_done = 0u;
        }
        for (int jz = t; jz < KK * DD; jz += 256) g_sums[jz] = 0.f;
        if (t < KK) g_counts[t] = 0.f;
    }
}

extern "C" void kernel_launch(void* const* d_in, const int* in_sizes, int n_in,
                              void* d_out, int out_size) {
    const float* data   = (const float*)d_in[0];
    const int*   labels = (const int*)d_in[1];
    const int    npts   = in_sizes[1];          // 512*1024
    float* out = (float*)d_out;

    k_sums<<<888, 256>>>(data, labels, npts);
    const int vblocks = npts / (256 * 4);       // 512, exact coverage
    k_var<<<vblocks, 256>>>(data, labels, npts, out);
}

// round 5
// speedup vs baseline: 1.2452x; 1.0481x over previous
#include <cuda_runtime.h>
#include <cuda_bf16.h>

// DiscriminativeLoss, two kernels, occupancy/MLP rebalanced.
//   data  : [D=32][N=524288] float32 (dim-major), labels: [N] int32 in [0,16)
//
// K1 (k_sums): TILE=128 -> 19KB smem, 6 blocks/SM (75% occ). Per tile:
// v[4] front-batched LDG.128 -> STS.128, counting-sort indices by label,
// thread (k, dr) walks list k for dims dr, dr+16.
// K2 (k_var): 2 pts/thread, 42-reg cap -> 6 blocks/SM (75% occ), 4 chunks
// of 8 front-batched LDG.64s (burst MLP=8/warp). Centers in smem [d][k].
// Last block adds dist+reg, writes out[0], resets globals (replay invariant).

#define DD 32
#define KK 16
#define TILE 128
#define XSTR 132   // 128+4: float4-aligned stores, banks spread by 4d+idx

__device__ float g_sums[KK * DD];   // [k][d]
__device__ float g_counts[KK];
__device__ float g_var;
__device__ unsigned int g_done;

__global__ __launch_bounds__(256, 6)
void k_sums(const float* __restrict__ data, const int* __restrict__ labels, int npts) {
    __shared__ float s_x[DD * XSTR];            // 16.9 KB
    __shared__ unsigned char s_list[KK][TILE];  // 2 KB
    __shared__ int s_cnt[KK];

    const int t  = threadIdx.x;
    const int k  = t >> 4;    // cluster this thread owns
    const int dr = t & 15;    // dims dr and dr+16

    float acc0 = 0.f, acc1 = 0.f;
    int ccnt = 0;

    const int ntiles = npts / TILE;             // 4096
    for (int tile = blockIdx.x; tile < ntiles; tile += gridDim.x) {
        const int n0 = tile * TILE;
        __syncthreads();                        // prev phase-B readers done
        if (t < KK) s_cnt[t] = 0;

        // Front-batched loads: 4 independent LDG.128 before any store
        float4 v[4];
        #pragma unroll
        for (int j = 0; j < 4; j++) {
            int idx = t + j * 256;              // 0..1023
            v[j] = *reinterpret_cast<const float4*>(
                data + (size_t)(idx >> 5) * npts + n0 + ((idx & 31) << 2));
        }
        int lab = (t < TILE) ? labels[n0 + t] : 0;
        #pragma unroll
        for (int j = 0; j < 4; j++) {
            int idx = t + j * 256;
            *reinterpret_cast<float4*>(
                s_x + (idx >> 5) * XSTR + ((idx & 31) << 2)) = v[j];
        }
        __syncthreads();                        // s_cnt zeroed, s_x filled

        // Phase A: compact point indices into per-label lists
        if (t < TILE) {
            int pos = atomicAdd(&s_cnt[lab], 1);
            s_list[lab][pos] = (unsigned char)t;
        }
        __syncthreads();                        // lists ready

        // Phase B: thread (k, dr) sums its cluster's points, 2 dims each
        const int cnt = s_cnt[k];
        const float* r0 = s_x + dr * XSTR;
        const float* r1 = s_x + (dr + 16) * XSTR;
        const unsigned char* lst = s_list[k];
        for (int i = 0; i < cnt; i++) {
            int idx = lst[i];
            acc0 += r0[idx];
            acc1 += r1[idx];
        }
        if (dr == 0) ccnt += cnt;
    }
    atomicAdd(&g_sums[k * DD + dr], acc0);
    atomicAdd(&g_sums[k * DD + dr + 16], acc1);
    if (dr == 0) atomicAdd(&g_counts[k], (float)ccnt);
}

__global__ __launch_bounds__(256, 6)
void k_var(const float* __restrict__ data, const int* __restrict__ labels,
           int npts, float* __restrict__ out) {
    __shared__ float s_c[DD * KK];   // [d][k]: 16-entry rows, conflict-free
    __shared__ float s_red[8];
    __shared__ float s_reg[KK];
    __shared__ unsigned int s_rank;
    const int t = threadIdx.x;

    // Every block derives centers (512 divides, trivial)
    #pragma unroll
    for (int j = t; j < DD * KK; j += 256) {
        int d = j >> 4, kk = j & 15;
        s_c[j] = g_sums[kk * DD + d] / g_counts[kk];
    }
    __syncthreads();

    // One pair of points per thread; grid covers exactly.
    const int n = (blockIdx.x * 256 + t) * 2;
    const int2 lab = *reinterpret_cast<const int2*>(labels + n);
    float a0 = 0.f, a1 = 0.f;

    #pragma unroll
    for (int c = 0; c < 4; c++) {
        // Loads-only: 8 independent LDG.64s issued before any use
        float2 v[8];
        #pragma unroll
        for (int j = 0; j < 8; j++)
            v[j] = *reinterpret_cast<const float2*>(
                data + (size_t)(c * 8 + j) * npts + n);
        #pragma unroll
        for (int j = 0; j < 8; j++) {
            const float* cr = s_c + (c * 8 + j) * KK;
            float d0 = cr[lab.x] - v[j].x; a0 = fmaf(d0, d0, a0);
            float d1 = cr[lab.y] - v[j].y; a1 = fmaf(d1, d1, a1);
        }
    }
    float h0 = fmaxf(sqrtf(a0) - 0.5f, 0.f);
    float h1 = fmaxf(sqrtf(a1) - 0.5f, 0.f);
    float vsum = h0 * h0 + h1 * h1;

    #pragma unroll
    for (int off = 16; off > 0; off >>= 1)
        vsum += __shfl_down_sync(0xffffffffu, vsum, off);
    if ((t & 31) == 0) s_red[t >> 5] = vsum;
    __syncthreads();
    if (t == 0) {
        float tot = 0.f;
        #pragma unroll
        for (int w = 0; w < 8; w++) tot += s_red[w];
        atomicAdd(&g_var, tot);
        __threadfence();
        s_rank = atomicAdd(&g_done, 1u);
    }
    __syncthreads();

    // Last block: dist + reg terms, final write, re-zero for replay
    if (s_rank == gridDim.x - 1) {
        __threadfence();
        __syncthreads();                 // make s_red reusable
        if (t < KK) {
            float s = 0.f;
            #pragma unroll
            for (int d = 0; d < DD; d++) { float c = s_c[d * KK + t]; s += c * c; }
            s_reg[t] = sqrtf(s);
        }
        const int i = t >> 4, j = t & 15;
        float dsum = 0.f;
        if (i != j) {
            float sq = 0.f;
            #pragma unroll
            for (int d = 0; d < DD; d++) {
                float df = s_c[d * KK + i] - s_c[d * KK + j];
                sq += df * df;
            }
            float h = fmaxf(3.0f - sqrtf(sq), 0.f);   // 2*DELTA_DIST
            dsum = h * h;
        }
        #pragma unroll
        for (int off = 16; off > 0; off >>= 1)
            dsum += __shfl_down_sync(0xffffffffu, dsum, off);
        if ((t & 31) == 0) s_red[t >> 5] = dsum;
        __syncthreads();
        if (t == 0) {
            float dtot = 0.f;
            #pragma unroll
            for (int w = 0; w < 8; w++) dtot += s_red[w];
            float reg = 0.f;
            #pragma unroll
            for (int kk = 0; kk < KK; kk++) reg += s_reg[kk];
            out[0] = g_var * (1.0f / KK)
                   + dtot * (1.0f / (KK * (KK - 1)))
                   + 0.001f * reg * (1.0f / KK);
            g_var = 0.f;
            g_done = 0u;
        }
        for (int jz = t; jz < KK * DD; jz += 256) g_sums[jz] = 0.f;
        if (t < KK) g_counts[t] = 0.f;
    }
}

extern "C" void kernel_launch(void* const* d_in, const int* in_sizes, int n_in,
                              void* d_out, int out_size) {
    const float* data   = (const float*)d_in[0];
    const int*   labels = (const int*)d_in[1];
    const int    npts   = in_sizes[1];          // 512*1024
    float* out = (float*)d_out;

    k_sums<<<888, 256>>>(data, labels, npts);   // 6 blocks/SM
    const int vblocks = npts / (256 * 2);       // 1024, exact coverage
    k_var<<<vblocks, 256>>>(data, labels, npts, out);
}